// round 16
// baseline (speedup 1.0000x reference)
#include <cuda_runtime.h>
#include <cuda_fp16.h>
#include <cstdint>

// NetVLAD fused warp-MMA kernel v13: R14 (affine padded-stride layouts) +
// log2e folded into W (raw ex2 softmax) + zero-C first MMA in GEMM1.
// 2 CTAs/SM, 4-way split, fused finalize.
// x:[64,128,64,64] fp32, conv_w:[64,128], centroids:[64,128] -> out:[64,8192] fp32

#define NB      64
#define CC      128
#define KK      64
#define SS      4096
#define SPLITS  4
#define SPER    (SS / SPLITS)   // 1024
#define TP      128             // pixels per tile
#define NTILES  (SPER / TP)     // 8
#define THREADS 256

#define XROW    272              // [c][p] and W row stride (256B data + 16 pad)
#define AROW    144              // a [p][k] row stride (128B data + 16 pad)

// SMEM layout (bytes)
#define OFF_XB0  0                          // 128 * 272 = 34816
#define OFF_XB1  34816
#define OFF_W    69632                      // 64 * 272 = 17408
#define OFF_A    87040                      // 128 * 144 = 18432
#define OFF_ASUM 105472                     // 64 floats
#define SMEM_BYTES (OFF_ASUM + 256)

#define LOG2E 1.4426950408889634f

__device__ float g_vlad_part[SPLITS * NB * KK * CC];   // [part][n][k][c]
__device__ float g_asum_part[SPLITS * NB * KK];
__device__ unsigned int g_flag[NB];

__device__ __forceinline__ uint32_t smem_u32(const void* p) {
    uint32_t a;
    asm("{ .reg .u64 t; cvta.to.shared.u64 t, %1; cvt.u32.u64 %0, t; }" : "=r"(a) : "l"(p));
    return a;
}
__device__ __forceinline__ float ex2(float v) {
    float r;
    asm("ex2.approx.f32 %0, %1;" : "=f"(r) : "f"(v));
    return r;
}

#define LDSM_X4(R, addr) \
    asm volatile("ldmatrix.sync.aligned.m8n8.x4.shared.b16 {%0,%1,%2,%3}, [%4];" \
        : "=r"((R)[0]), "=r"((R)[1]), "=r"((R)[2]), "=r"((R)[3]) : "r"(addr))
#define LDSM_X4T(R, addr) \
    asm volatile("ldmatrix.sync.aligned.m8n8.x4.trans.shared.b16 {%0,%1,%2,%3}, [%4];" \
        : "=r"((R)[0]), "=r"((R)[1]), "=r"((R)[2]), "=r"((R)[3]) : "r"(addr))

__device__ __forceinline__ void mma16816(float* d, const uint32_t* a,
                                         uint32_t b0, uint32_t b1) {
    asm volatile(
        "mma.sync.aligned.m16n8k16.row.col.f32.f16.f16.f32 "
        "{%0,%1,%2,%3}, {%4,%5,%6,%7}, {%8,%9}, {%0,%1,%2,%3};"
        : "+f"(d[0]), "+f"(d[1]), "+f"(d[2]), "+f"(d[3])
        : "r"(a[0]), "r"(a[1]), "r"(a[2]), "r"(a[3]), "r"(b0), "r"(b1));
}
// first K-step: C = 0 (no accumulator init needed)
__device__ __forceinline__ void mma16816_z(float* d, const uint32_t* a,
                                           uint32_t b0, uint32_t b1) {
    asm volatile(
        "mma.sync.aligned.m16n8k16.row.col.f32.f16.f16.f32 "
        "{%0,%1,%2,%3}, {%4,%5,%6,%7}, {%8,%9}, {%10,%10,%10,%10};"
        : "=f"(d[0]), "=f"(d[1]), "=f"(d[2]), "=f"(d[3])
        : "r"(a[0]), "r"(a[1]), "r"(a[2]), "r"(a[3]), "r"(b0), "r"(b1), "f"(0.f));
}

// result = { lo = f16(lo_f), hi = f16(hi_f) }
__device__ __forceinline__ uint32_t pack_f16x2(float lo_f, float hi_f) {
    uint32_t r;
    asm("cvt.rn.f16x2.f32 %0, %1, %2;" : "=r"(r) : "f"(hi_f), "f"(lo_f));
    return r;
}

__global__ void __launch_bounds__(THREADS, 2)
netvlad_mma(const float* __restrict__ x, const float* __restrict__ conv_w,
            const float* __restrict__ centroids, float* __restrict__ out) {
    extern __shared__ char smem[];
    const uint32_t sb = smem_u32(smem);
    const int tid  = threadIdx.x;
    const int lane = tid & 31;
    const int warp = tid >> 5;
    const int split = blockIdx.x;
    const int n     = blockIdx.y;

    if (tid < KK) ((float*)(smem + OFF_ASUM))[tid] = 0.f;

    // conv_w [64][128] -> fp16 [k][c] * log2e, 272B-stride rows (conflict-free)
    for (int i = tid; i < KK * CC / 2; i += THREADS) {
        int k = i >> 6, c2 = (i & 63) * 2;
        float2 v = *(const float2*)(conv_w + k * CC + c2);
        *(uint32_t*)(smem + OFF_W + k * XROW + c2 * 2) =
            pack_f16x2(v.x * LOG2E, v.y * LOG2E);
    }

    const float* xb_g = x + ((size_t)n * CC) * SS + (size_t)split * SPER;

    // prologue: load tile 0 into XB0 ([c][p] layout, 272B-stride rows)
    #pragma unroll
    for (int ridx = 0; ridx < 16; ++ridx) {
        int c = (ridx >> 3) * 64 + warp * 8 + (ridx & 7);
        float4 v = *(const float4*)(xb_g + (size_t)c * SS + lane * 4);
        uint2 pk;
        pk.x = pack_f16x2(v.x, v.y);
        pk.y = pack_f16x2(v.z, v.w);
        *(uint2*)(smem + OFF_XB0 + c * XROW + lane * 8) = pk;
    }
    __syncthreads();

    float vacc[32];
    #pragma unroll
    for (int i = 0; i < 32; i++) vacc[i] = 0.f;
    float asum[16];
    #pragma unroll
    for (int i = 0; i < 16; i++) asum[i] = 0.f;

    const int kg2 = warp & 1;   // GEMM2 k-half (32 clusters)
    const int cg2 = warp >> 1;  // GEMM2 c-quarter (32 channels)
    const int wp  = warp * 16;  // GEMM1 pixel base

    for (int t = 0; t < NTILES; ++t) {
        const uint32_t xboff  = OFF_XB0 + (uint32_t)(t & 1) * 34816;
        const uint32_t nxboff = OFF_XB0 + (uint32_t)((t + 1) & 1) * 34816;
        const bool pf = (t + 1 < NTILES);
        const float* xnext = xb_g + (size_t)(t + 1) * TP;

        if (t > 0) __syncthreads();   // sync#1: XB(t) visible, A(t-1) reads done

        // ---- GEMM1: logits2[p][k] = x^T . (w*log2e)^T ; prefetch 1 row/ks ----
        float lacc[32];

        #pragma unroll
        for (int ks = 0; ks < 8; ++ks) {
            uint32_t ah[4];
            {
                int arow = ks * 16 + (lane & 7) + (lane >> 4) * 8;
                int abyte = wp * 2 + ((lane >> 3) & 1) * 16;
                LDSM_X4T(ah, sb + xboff + arow * XROW + abyte);
            }
            uint32_t bh[16];
            #pragma unroll
            for (int np = 0; np < 4; ++np) {
                int brow = np * 16 + (lane & 7) + ((lane >> 4) & 1) * 8;
                int bbyte = ks * 32 + ((lane >> 3) & 1) * 16;
                LDSM_X4(bh + np * 4, sb + OFF_W + brow * XROW + bbyte);
            }
            if (pf) {   // prefetch channel row (first half) of tile t+1
                int c = warp * 8 + ks;
                float4 v = *(const float4*)(xnext + (size_t)c * SS + lane * 4);
                uint2 pk;
                pk.x = pack_f16x2(v.x, v.y);
                pk.y = pack_f16x2(v.z, v.w);
                *(uint2*)(smem + nxboff + c * XROW + lane * 8) = pk;
            }
            #pragma unroll
            for (int nt = 0; nt < 8; ++nt) {
                int bi = (nt >> 1) * 4 + (nt & 1) * 2;
                if (ks == 0) mma16816_z(lacc + nt * 4, ah, bh[bi], bh[bi + 1]);
                else         mma16816(lacc + nt * 4, ah, bh[bi], bh[bi + 1]);
            }
        }

        // ---- softmax over K: a = 2^l2 / sum (W pre-scaled by log2e) ----
        float s1 = 0.f, s2 = 0.f;
        #pragma unroll
        for (int nt = 0; nt < 8; ++nt) {
            float e0 = ex2(lacc[nt * 4 + 0]);
            float e1 = ex2(lacc[nt * 4 + 1]);
            float e2 = ex2(lacc[nt * 4 + 2]);
            float e3 = ex2(lacc[nt * 4 + 3]);
            lacc[nt * 4 + 0] = e0; lacc[nt * 4 + 1] = e1;
            lacc[nt * 4 + 2] = e2; lacc[nt * 4 + 3] = e3;
            s1 += e0 + e1; s2 += e2 + e3;
        }
        #pragma unroll
        for (int o = 1; o <= 2; o <<= 1) {
            s1 += __shfl_xor_sync(0xFFFFFFFFu, s1, o);
            s2 += __shfl_xor_sync(0xFFFFFFFFu, s2, o);
        }
        const float i1 = 1.f / s1, i2 = 1.f / s2;

        // ---- a -> SMEM [p][k]: direct packed (k,k+1) stores, no shfl ----
        {
            const int p1 = wp + (lane >> 2);      // row for regs c0,c1
            const int p2 = p1 + 8;                // row for regs c2,c3
            #pragma unroll
            for (int nt = 0; nt < 8; ++nt) {
                float a0 = lacc[nt * 4 + 0] * i1, a1 = lacc[nt * 4 + 1] * i1;
                float a2 = lacc[nt * 4 + 2] * i2, a3 = lacc[nt * 4 + 3] * i2;
                asum[nt * 2 + 0] += a0 + a2;
                asum[nt * 2 + 1] += a1 + a3;
                int kb = nt * 16 + (lane & 3) * 4;      // byte of k-pair
                *(uint32_t*)(smem + OFF_A + p1 * AROW + kb) = pack_f16x2(a0, a1);
                *(uint32_t*)(smem + OFF_A + p2 * AROW + kb) = pack_f16x2(a2, a3);
            }
        }
        __syncthreads();   // sync#2: a visible

        // ---- GEMM2 (32k x 32c per warp): vlad^T[k][c] += a . x ;
        //      prefetch 1 row/ps of x(t+1) (second half) ----
        #pragma unroll
        for (int ps = 0; ps < 8; ++ps) {
            uint32_t aah[8];
            #pragma unroll
            for (int mi = 0; mi < 2; ++mi) {
                int arow = ps * 16 + (lane & 7) + (lane >> 4) * 8;
                int abyte = kg2 * 64 + mi * 32 + ((lane >> 3) & 1) * 16;
                LDSM_X4T(aah + mi * 4, sb + OFF_A + arow * AROW + abyte);
            }
            uint32_t bxh[8];
            #pragma unroll
            for (int np = 0; np < 2; ++np) {
                int brow = cg2 * 32 + np * 16 + (lane & 7) + ((lane >> 4) & 1) * 8;
                int bbyte = ps * 32 + ((lane >> 3) & 1) * 16;
                LDSM_X4(bxh + np * 4, sb + xboff + brow * XROW + bbyte);
            }
            if (pf) {   // prefetch channel row (second half) of tile t+1
                int c = 64 + warp * 8 + ps;
                float4 v = *(const float4*)(xnext + (size_t)c * SS + lane * 4);
                uint2 pk;
                pk.x = pack_f16x2(v.x, v.y);
                pk.y = pack_f16x2(v.z, v.w);
                *(uint2*)(smem + nxboff + c * XROW + lane * 8) = pk;
            }
            #pragma unroll
            for (int mi = 0; mi < 2; ++mi)
                #pragma unroll
                for (int j = 0; j < 4; ++j) {
                    int bi = (j >> 1) * 4 + (j & 1) * 2;
                    mma16816(vacc + (mi * 4 + j) * 4, aah + mi * 4,
                             bxh[bi], bxh[bi + 1]);
                }
        }
    }

    // ---- write vlad partials [k][c] ----
    {
        float* dst = g_vlad_part + (size_t)(split * NB + n) * (KK * CC);
        #pragma unroll
        for (int mi = 0; mi < 2; ++mi)
            #pragma unroll
            for (int j = 0; j < 4; ++j) {
                int k1 = kg2 * 32 + mi * 16 + (lane >> 2), k2 = k1 + 8;
                int c = cg2 * 32 + j * 8 + (lane & 3) * 2;
                const float* va = vacc + (mi * 4 + j) * 4;
                *(float2*)(dst + k1 * CC + c) = make_float2(va[0], va[1]);
                *(float2*)(dst + k2 * CC + c) = make_float2(va[2], va[3]);
            }
    }
    // ---- asum: warp reduce + smem atomic combine ----
    #pragma unroll
    for (int i = 0; i < 16; ++i) {
        float s = asum[i];
        s += __shfl_xor_sync(0xFFFFFFFFu, s, 4);
        s += __shfl_xor_sync(0xFFFFFFFFu, s, 8);
        s += __shfl_xor_sync(0xFFFFFFFFu, s, 16);
        asum[i] = s;
    }
    if (lane < 4) {
        float* as = (float*)(smem + OFF_ASUM);
        #pragma unroll
        for (int nt = 0; nt < 8; ++nt) {
            atomicAdd(as + nt * 8 + lane * 2 + 0, asum[nt * 2 + 0]);
            atomicAdd(as + nt * 8 + lane * 2 + 1, asum[nt * 2 + 1]);
        }
    }
    __syncthreads();
    if (tid < KK)
        g_asum_part[(size_t)(split * NB + n) * KK + tid] = ((float*)(smem + OFF_ASUM))[tid];

    // ---- signal partials ready ----
    __threadfence();
    __syncthreads();
    if (tid == 0) atomicAdd(&g_flag[n], 1u);

    if (split != 0) return;

    // ================= fused finalize (split-0 CTA) =================
    if (tid == 0) { while (atomicAdd(&g_flag[n], 0u) < (unsigned)SPLITS) { } }
    __syncthreads();
    __threadfence();

    float* v      = (float*)(smem);                 // 32 KB (over XB0)
    float* fasum  = (float*)(smem + OFF_W);
    float* rowinv = (float*)(smem + OFF_W + 256);
    float* wsum   = (float*)(smem + OFF_W + 512);

    if (tid < KK) {
        float s = 0.f;
        #pragma unroll
        for (int pp = 0; pp < SPLITS; ++pp)
            s += g_asum_part[(size_t)(pp * NB + n) * KK + tid];
        fasum[tid] = s;
    }
    __syncthreads();

    for (int idx = tid; idx < KK * CC; idx += THREADS) {
        int k = idx >> 7;
        float s = 0.f;
        #pragma unroll
        for (int pp = 0; pp < SPLITS; ++pp)
            s += g_vlad_part[(size_t)(pp * NB + n) * (KK * CC) + idx];
        v[idx] = s - fasum[k] * centroids[idx];
    }
    __syncthreads();

    for (int k = warp; k < KK; k += THREADS / 32) {
        const float* row = v + k * CC;
        float s = 0.f;
        #pragma unroll
        for (int c = lane; c < CC; c += 32) { float tv = row[c]; s += tv * tv; }
        #pragma unroll
        for (int o = 16; o; o >>= 1) s += __shfl_xor_sync(0xFFFFFFFFu, s, o);
        if (lane == 0) rowinv[k] = rsqrtf(s);
    }
    __syncthreads();

    float local = 0.f;
    for (int idx = tid; idx < KK * CC; idx += THREADS) {
        float tv = v[idx] * rowinv[idx >> 7];
        v[idx] = tv;
        local += tv * tv;
    }
    #pragma unroll
    for (int o = 16; o; o >>= 1) local += __shfl_xor_sync(0xFFFFFFFFu, local, o);
    if (lane == 0) wsum[warp] = local;
    __syncthreads();
    if (tid == 0) {
        float s = 0.f;
        #pragma unroll
        for (int w = 0; w < THREADS / 32; ++w) s += wsum[w];
        wsum[0] = rsqrtf(s);
    }
    __syncthreads();
    const float ginv = wsum[0];

    for (int idx = tid; idx < KK * CC; idx += THREADS)
        out[(size_t)n * (KK * CC) + idx] = v[idx] * ginv;

    __syncthreads();
    if (tid == 0) atomicExch(&g_flag[n], 0u);   // reset for next graph replay
}

extern "C" void kernel_launch(void* const* d_in, const int* in_sizes, int n_in,
                              void* d_out, int out_size) {
    const float* x         = (const float*)d_in[0];
    const float* conv_w    = (const float*)d_in[1];
    const float* centroids = (const float*)d_in[2];
    float* out = (float*)d_out;

    cudaFuncSetAttribute(netvlad_mma, cudaFuncAttributeMaxDynamicSharedMemorySize, SMEM_BYTES);
    netvlad_mma<<<dim3(SPLITS, NB), THREADS, SMEM_BYTES>>>(x, conv_w, centroids, out);
}

// round 17
// speedup vs baseline: 1.0988x; 1.0988x over previous
#include <cuda_runtime.h>
#include <cuda_fp16.h>
#include <cstdint>

// NetVLAD fused warp-MMA kernel v14: exact R14 (affine padded-stride layouts,
// 1+1 prefetch, [p][k] a-layout) + log2e folded into W (ex2 softmax).
// 2 CTAs/SM, 4-way split, fused finalize.
// x:[64,128,64,64] fp32, conv_w:[64,128], centroids:[64,128] -> out:[64,8192] fp32

#define NB      64
#define CC      128
#define KK      64
#define SS      4096
#define SPLITS  4
#define SPER    (SS / SPLITS)   // 1024
#define TP      128             // pixels per tile
#define NTILES  (SPER / TP)     // 8
#define THREADS 256

#define XROW    272              // [c][p] and W row stride (256B data + 16 pad)
#define AROW    144              // a [p][k] row stride (128B data + 16 pad)

// SMEM layout (bytes)
#define OFF_XB0  0                          // 128 * 272 = 34816
#define OFF_XB1  34816
#define OFF_W    69632                      // 64 * 272 = 17408
#define OFF_A    87040                      // 128 * 144 = 18432
#define OFF_ASUM 105472                     // 64 floats
#define SMEM_BYTES (OFF_ASUM + 256)

#define LOG2E 1.4426950408889634f

__device__ float g_vlad_part[SPLITS * NB * KK * CC];   // [part][n][k][c]
__device__ float g_asum_part[SPLITS * NB * KK];
__device__ unsigned int g_flag[NB];

__device__ __forceinline__ uint32_t smem_u32(const void* p) {
    uint32_t a;
    asm("{ .reg .u64 t; cvta.to.shared.u64 t, %1; cvt.u32.u64 %0, t; }" : "=r"(a) : "l"(p));
    return a;
}
__device__ __forceinline__ float ex2(float v) {
    float r;
    asm("ex2.approx.f32 %0, %1;" : "=f"(r) : "f"(v));
    return r;
}

#define LDSM_X4(R, addr) \
    asm volatile("ldmatrix.sync.aligned.m8n8.x4.shared.b16 {%0,%1,%2,%3}, [%4];" \
        : "=r"((R)[0]), "=r"((R)[1]), "=r"((R)[2]), "=r"((R)[3]) : "r"(addr))
#define LDSM_X4T(R, addr) \
    asm volatile("ldmatrix.sync.aligned.m8n8.x4.trans.shared.b16 {%0,%1,%2,%3}, [%4];" \
        : "=r"((R)[0]), "=r"((R)[1]), "=r"((R)[2]), "=r"((R)[3]) : "r"(addr))

__device__ __forceinline__ void mma16816(float* d, const uint32_t* a,
                                         uint32_t b0, uint32_t b1) {
    asm volatile(
        "mma.sync.aligned.m16n8k16.row.col.f32.f16.f16.f32 "
        "{%0,%1,%2,%3}, {%4,%5,%6,%7}, {%8,%9}, {%0,%1,%2,%3};"
        : "+f"(d[0]), "+f"(d[1]), "+f"(d[2]), "+f"(d[3])
        : "r"(a[0]), "r"(a[1]), "r"(a[2]), "r"(a[3]), "r"(b0), "r"(b1));
}

// result = { lo = f16(lo_f), hi = f16(hi_f) }
__device__ __forceinline__ uint32_t pack_f16x2(float lo_f, float hi_f) {
    uint32_t r;
    asm("cvt.rn.f16x2.f32 %0, %1, %2;" : "=r"(r) : "f"(hi_f), "f"(lo_f));
    return r;
}

__global__ void __launch_bounds__(THREADS, 2)
netvlad_mma(const float* __restrict__ x, const float* __restrict__ conv_w,
            const float* __restrict__ centroids, float* __restrict__ out) {
    extern __shared__ char smem[];
    const uint32_t sb = smem_u32(smem);
    const int tid  = threadIdx.x;
    const int lane = tid & 31;
    const int warp = tid >> 5;
    const int split = blockIdx.x;
    const int n     = blockIdx.y;

    if (tid < KK) ((float*)(smem + OFF_ASUM))[tid] = 0.f;

    // conv_w [64][128] -> fp16 [k][c] * log2e, 272B-stride rows (conflict-free)
    for (int i = tid; i < KK * CC / 2; i += THREADS) {
        int k = i >> 6, c2 = (i & 63) * 2;
        float2 v = *(const float2*)(conv_w + k * CC + c2);
        *(uint32_t*)(smem + OFF_W + k * XROW + c2 * 2) =
            pack_f16x2(v.x * LOG2E, v.y * LOG2E);
    }

    const float* xb_g = x + ((size_t)n * CC) * SS + (size_t)split * SPER;

    // prologue: load tile 0 into XB0 ([c][p] layout, 272B-stride rows)
    #pragma unroll
    for (int ridx = 0; ridx < 16; ++ridx) {
        int c = (ridx >> 3) * 64 + warp * 8 + (ridx & 7);
        float4 v = *(const float4*)(xb_g + (size_t)c * SS + lane * 4);
        uint2 pk;
        pk.x = pack_f16x2(v.x, v.y);
        pk.y = pack_f16x2(v.z, v.w);
        *(uint2*)(smem + OFF_XB0 + c * XROW + lane * 8) = pk;
    }
    __syncthreads();

    float vacc[32];
    #pragma unroll
    for (int i = 0; i < 32; i++) vacc[i] = 0.f;
    float asum[16];
    #pragma unroll
    for (int i = 0; i < 16; i++) asum[i] = 0.f;

    const int kg2 = warp & 1;   // GEMM2 k-half (32 clusters)
    const int cg2 = warp >> 1;  // GEMM2 c-quarter (32 channels)
    const int wp  = warp * 16;  // GEMM1 pixel base

    for (int t = 0; t < NTILES; ++t) {
        const uint32_t xboff  = OFF_XB0 + (uint32_t)(t & 1) * 34816;
        const uint32_t nxboff = OFF_XB0 + (uint32_t)((t + 1) & 1) * 34816;
        const bool pf = (t + 1 < NTILES);
        const float* xnext = xb_g + (size_t)(t + 1) * TP;

        if (t > 0) __syncthreads();   // sync#1: XB(t) visible, A(t-1) reads done

        // ---- GEMM1: logits2[p][k] = x^T . (w*log2e)^T ; prefetch 1 row/ks ----
        float lacc[32];
        #pragma unroll
        for (int i = 0; i < 32; i++) lacc[i] = 0.f;

        #pragma unroll
        for (int ks = 0; ks < 8; ++ks) {
            uint32_t ah[4];
            {
                int arow = ks * 16 + (lane & 7) + (lane >> 4) * 8;
                int abyte = wp * 2 + ((lane >> 3) & 1) * 16;
                LDSM_X4T(ah, sb + xboff + arow * XROW + abyte);
            }
            uint32_t bh[16];
            #pragma unroll
            for (int np = 0; np < 4; ++np) {
                int brow = np * 16 + (lane & 7) + ((lane >> 4) & 1) * 8;
                int bbyte = ks * 32 + ((lane >> 3) & 1) * 16;
                LDSM_X4(bh + np * 4, sb + OFF_W + brow * XROW + bbyte);
            }
            if (pf) {   // prefetch channel row (first half) of tile t+1
                int c = warp * 8 + ks;
                float4 v = *(const float4*)(xnext + (size_t)c * SS + lane * 4);
                uint2 pk;
                pk.x = pack_f16x2(v.x, v.y);
                pk.y = pack_f16x2(v.z, v.w);
                *(uint2*)(smem + nxboff + c * XROW + lane * 8) = pk;
            }
            #pragma unroll
            for (int nt = 0; nt < 8; ++nt) {
                int bi = (nt >> 1) * 4 + (nt & 1) * 2;
                mma16816(lacc + nt * 4, ah, bh[bi], bh[bi + 1]);
            }
        }

        // ---- softmax over K: a = 2^l2 / sum (W pre-scaled by log2e) ----
        float s1 = 0.f, s2 = 0.f;
        #pragma unroll
        for (int nt = 0; nt < 8; ++nt) {
            float e0 = ex2(lacc[nt * 4 + 0]);
            float e1 = ex2(lacc[nt * 4 + 1]);
            float e2 = ex2(lacc[nt * 4 + 2]);
            float e3 = ex2(lacc[nt * 4 + 3]);
            lacc[nt * 4 + 0] = e0; lacc[nt * 4 + 1] = e1;
            lacc[nt * 4 + 2] = e2; lacc[nt * 4 + 3] = e3;
            s1 += e0 + e1; s2 += e2 + e3;
        }
        #pragma unroll
        for (int o = 1; o <= 2; o <<= 1) {
            s1 += __shfl_xor_sync(0xFFFFFFFFu, s1, o);
            s2 += __shfl_xor_sync(0xFFFFFFFFu, s2, o);
        }
        const float i1 = 1.f / s1, i2 = 1.f / s2;

        // ---- a -> SMEM [p][k]: direct packed (k,k+1) stores, no shfl ----
        {
            const int p1 = wp + (lane >> 2);      // row for regs c0,c1
            const int p2 = p1 + 8;                // row for regs c2,c3
            #pragma unroll
            for (int nt = 0; nt < 8; ++nt) {
                float a0 = lacc[nt * 4 + 0] * i1, a1 = lacc[nt * 4 + 1] * i1;
                float a2 = lacc[nt * 4 + 2] * i2, a3 = lacc[nt * 4 + 3] * i2;
                asum[nt * 2 + 0] += a0 + a2;
                asum[nt * 2 + 1] += a1 + a3;
                int kb = nt * 16 + (lane & 3) * 4;      // byte of k-pair
                *(uint32_t*)(smem + OFF_A + p1 * AROW + kb) = pack_f16x2(a0, a1);
                *(uint32_t*)(smem + OFF_A + p2 * AROW + kb) = pack_f16x2(a2, a3);
            }
        }
        __syncthreads();   // sync#2: a visible

        // ---- GEMM2 (32k x 32c per warp): vlad^T[k][c] += a . x ;
        //      prefetch 1 row/ps of x(t+1) (second half) ----
        #pragma unroll
        for (int ps = 0; ps < 8; ++ps) {
            uint32_t aah[8];
            #pragma unroll
            for (int mi = 0; mi < 2; ++mi) {
                int arow = ps * 16 + (lane & 7) + (lane >> 4) * 8;
                int abyte = kg2 * 64 + mi * 32 + ((lane >> 3) & 1) * 16;
                LDSM_X4T(aah + mi * 4, sb + OFF_A + arow * AROW + abyte);
            }
            uint32_t bxh[8];
            #pragma unroll
            for (int np = 0; np < 2; ++np) {
                int brow = cg2 * 32 + np * 16 + (lane & 7) + ((lane >> 4) & 1) * 8;
                int bbyte = ps * 32 + ((lane >> 3) & 1) * 16;
                LDSM_X4(bxh + np * 4, sb + xboff + brow * XROW + bbyte);
            }
            if (pf) {   // prefetch channel row (second half) of tile t+1
                int c = 64 + warp * 8 + ps;
                float4 v = *(const float4*)(xnext + (size_t)c * SS + lane * 4);
                uint2 pk;
                pk.x = pack_f16x2(v.x, v.y);
                pk.y = pack_f16x2(v.z, v.w);
                *(uint2*)(smem + nxboff + c * XROW + lane * 8) = pk;
            }
            #pragma unroll
            for (int mi = 0; mi < 2; ++mi)
                #pragma unroll
                for (int j = 0; j < 4; ++j) {
                    int bi = (j >> 1) * 4 + (j & 1) * 2;
                    mma16816(vacc + (mi * 4 + j) * 4, aah + mi * 4,
                             bxh[bi], bxh[bi + 1]);
                }
        }
    }

    // ---- write vlad partials [k][c] ----
    {
        float* dst = g_vlad_part + (size_t)(split * NB + n) * (KK * CC);
        #pragma unroll
        for (int mi = 0; mi < 2; ++mi)
            #pragma unroll
            for (int j = 0; j < 4; ++j) {
                int k1 = kg2 * 32 + mi * 16 + (lane >> 2), k2 = k1 + 8;
                int c = cg2 * 32 + j * 8 + (lane & 3) * 2;
                const float* va = vacc + (mi * 4 + j) * 4;
                *(float2*)(dst + k1 * CC + c) = make_float2(va[0], va[1]);
                *(float2*)(dst + k2 * CC + c) = make_float2(va[2], va[3]);
            }
    }
    // ---- asum: warp reduce + smem atomic combine ----
    #pragma unroll
    for (int i = 0; i < 16; ++i) {
        float s = asum[i];
        s += __shfl_xor_sync(0xFFFFFFFFu, s, 4);
        s += __shfl_xor_sync(0xFFFFFFFFu, s, 8);
        s += __shfl_xor_sync(0xFFFFFFFFu, s, 16);
        asum[i] = s;
    }
    if (lane < 4) {
        float* as = (float*)(smem + OFF_ASUM);
        #pragma unroll
        for (int nt = 0; nt < 8; ++nt) {
            atomicAdd(as + nt * 8 + lane * 2 + 0, asum[nt * 2 + 0]);
            atomicAdd(as + nt * 8 + lane * 2 + 1, asum[nt * 2 + 1]);
        }
    }
    __syncthreads();
    if (tid < KK)
        g_asum_part[(size_t)(split * NB + n) * KK + tid] = ((float*)(smem + OFF_ASUM))[tid];

    // ---- signal partials ready ----
    __threadfence();
    __syncthreads();
    if (tid == 0) atomicAdd(&g_flag[n], 1u);

    if (split != 0) return;

    // ================= fused finalize (split-0 CTA) =================
    if (tid == 0) { while (atomicAdd(&g_flag[n], 0u) < (unsigned)SPLITS) { } }
    __syncthreads();
    __threadfence();

    float* v      = (float*)(smem);                 // 32 KB (over XB0)
    float* fasum  = (float*)(smem + OFF_W);
    float* rowinv = (float*)(smem + OFF_W + 256);
    float* wsum   = (float*)(smem + OFF_W + 512);

    if (tid < KK) {
        float s = 0.f;
        #pragma unroll
        for (int pp = 0; pp < SPLITS; ++pp)
            s += g_asum_part[(size_t)(pp * NB + n) * KK + tid];
        fasum[tid] = s;
    }
    __syncthreads();

    for (int idx = tid; idx < KK * CC; idx += THREADS) {
        int k = idx >> 7;
        float s = 0.f;
        #pragma unroll
        for (int pp = 0; pp < SPLITS; ++pp)
            s += g_vlad_part[(size_t)(pp * NB + n) * (KK * CC) + idx];
        v[idx] = s - fasum[k] * centroids[idx];
    }
    __syncthreads();

    for (int k = warp; k < KK; k += THREADS / 32) {
        const float* row = v + k * CC;
        float s = 0.f;
        #pragma unroll
        for (int c = lane; c < CC; c += 32) { float tv = row[c]; s += tv * tv; }
        #pragma unroll
        for (int o = 16; o; o >>= 1) s += __shfl_xor_sync(0xFFFFFFFFu, s, o);
        if (lane == 0) rowinv[k] = rsqrtf(s);
    }
    __syncthreads();

    float local = 0.f;
    for (int idx = tid; idx < KK * CC; idx += THREADS) {
        float tv = v[idx] * rowinv[idx >> 7];
        v[idx] = tv;
        local += tv * tv;
    }
    #pragma unroll
    for (int o = 16; o; o >>= 1) local += __shfl_xor_sync(0xFFFFFFFFu, local, o);
    if (lane == 0) wsum[warp] = local;
    __syncthreads();
    if (tid == 0) {
        float s = 0.f;
        #pragma unroll
        for (int w = 0; w < THREADS / 32; ++w) s += wsum[w];
        wsum[0] = rsqrtf(s);
    }
    __syncthreads();
    const float ginv = wsum[0];

    for (int idx = tid; idx < KK * CC; idx += THREADS)
        out[(size_t)n * (KK * CC) + idx] = v[idx] * ginv;

    __syncthreads();
    if (tid == 0) atomicExch(&g_flag[n], 0u);   // reset for next graph replay
}

extern "C" void kernel_launch(void* const* d_in, const int* in_sizes, int n_in,
                              void* d_out, int out_size) {
    const float* x         = (const float*)d_in[0];
    const float* conv_w    = (const float*)d_in[1];
    const float* centroids = (const float*)d_in[2];
    float* out = (float*)d_out;

    cudaFuncSetAttribute(netvlad_mma, cudaFuncAttributeMaxDynamicSharedMemorySize, SMEM_BYTES);
    netvlad_mma<<<dim3(SPLITS, NB), THREADS, SMEM_BYTES>>>(x, conv_w, centroids, out);
}